// round 3
// baseline (speedup 1.0000x reference)
#include <cuda_runtime.h>
#include <math_constants.h>

#define NN   50000
#define EE   1600000
#define ETOT 1650000      // EE + NN self loops
#define INCH 34
#define H1   2
#define C1   64
#define F1   128          // layer1 concat width
#define F2   64           // layer2 out width
#define NEG  0.2f

// ---- scratch (static device globals; no runtime allocation) ----
__device__ float g_xw1 [NN * F1];    // x @ W1                [N,128]
__device__ float g_hacc[NN * F1];    // layer1 aggregation    [N,128]
__device__ float g_xw2 [NN * F2];    // relu(h+b1) @ W2       [N,64]
__device__ float g_al1s[NN * H1];
__device__ float g_al1d[NN * H1];
__device__ float g_al2s[NN];
__device__ float g_al2d[NN];
__device__ int   g_cnt [NN];         // dst histogram
__device__ int   g_off [NN + 1];     // CSR offsets
__device__ int   g_cur [NN];         // scatter cursors
__device__ int   g_src [ETOT];       // decoded src per original edge
__device__ int   g_dst [ETOT];       // decoded dst per original edge
__device__ int   g_esrc[ETOT];       // src index per edge, bucketed by dst
__device__ int   g_is64;             // edge_index dtype flag

__device__ __forceinline__ float lrelu(float v){ return v >= 0.f ? v : NEG * v; }

// ---------------- dtype detect (1 thread) ----------------
__global__ void kdetect(const void* __restrict__ ei){
    const long long* p = (const long long*)ei;
    bool ok64 = true;
    #pragma unroll
    for (int i = 0; i < 64; i++){
        long long v = p[i];
        if (v < 0 || v >= NN) ok64 = false;
    }
    g_is64 = ok64 ? 1 : 0;
}

// ---------------- init: zero histogram ----------------
__global__ void kinit(){
    int i = blockIdx.x * blockDim.x + threadIdx.x;
    if (i < NN) g_cnt[i] = 0;
}

// ---------------- decode edges (+ fused dst histogram) ----------------
__global__ void kconv(const void* __restrict__ ei){
    int e = blockIdx.x * blockDim.x + threadIdx.x;
    if (e >= ETOT) return;
    int s, d;
    if (e < EE){
        if (g_is64){
            const long long* p = (const long long*)ei;
            s = (int)p[e]; d = (int)p[EE + e];
        } else {
            const int* p = (const int*)ei;
            s = p[e]; d = p[EE + e];
        }
    } else {
        s = e - EE; d = s;
    }
    g_src[e] = s; g_dst[e] = d;
    atomicAdd(&g_cnt[d], 1);
}

// ---------------- layer1 projection + logits ----------------
__global__ void k1(const float* __restrict__ x, const float* __restrict__ W1,
                   const float* __restrict__ as1, const float* __restrict__ ad1){
    __shared__ float sx[INCH];
    __shared__ float rs[F1], rd[F1];
    int n = blockIdx.x, c = threadIdx.x;           // 128 threads
    if (c < INCH) sx[c] = x[n * INCH + c];
    __syncthreads();
    float acc = 0.f;
    #pragma unroll
    for (int k = 0; k < INCH; k++) acc = fmaf(sx[k], W1[k * F1 + c], acc);
    g_xw1[n * F1 + c] = acc;
    int h = c >> 6, cc = c & 63;
    rs[c] = acc * as1[h * C1 + cc];
    rd[c] = acc * ad1[h * C1 + cc];
    __syncthreads();
    if ((c & 63) < 32){                            // warps 0 and 2, fully active
        float vs = rs[c] + rs[c + 32];
        float vd = rd[c] + rd[c + 32];
        #pragma unroll
        for (int off = 16; off; off >>= 1){
            vs += __shfl_down_sync(0xffffffffu, vs, off);
            vd += __shfl_down_sync(0xffffffffu, vd, off);
        }
        if ((c & 31) == 0){ g_al1s[n * 2 + h] = vs; g_al1d[n * 2 + h] = vd; }
    }
}

// ---------------- CSR: scan + scatter ----------------
// single block, 1024 threads: exclusive scan of g_cnt -> g_off (+ g_cur copy)
__global__ void kscan(){
    __shared__ int ssum[1024];
    const int CH = (NN + 1023) / 1024;             // 49
    int t = threadIdx.x;
    int base = t * CH;
    int s = 0;
    for (int i = 0; i < CH; i++){ int idx = base + i; if (idx < NN) s += g_cnt[idx]; }
    ssum[t] = s;
    __syncthreads();
    for (int off = 1; off < 1024; off <<= 1){
        int v = (t >= off) ? ssum[t - off] : 0;
        __syncthreads();
        ssum[t] += v;
        __syncthreads();
    }
    int run = (t == 0) ? 0 : ssum[t - 1];
    for (int i = 0; i < CH; i++){
        int idx = base + i;
        if (idx < NN){ g_off[idx] = run; g_cur[idx] = run; run += g_cnt[idx]; }
    }
    if (t == 1023) g_off[NN] = ssum[1023];
}

__global__ void kscatter(){
    int e = blockIdx.x * blockDim.x + threadIdx.x;
    if (e >= ETOT) return;
    int pos = atomicAdd(&g_cur[g_dst[e]], 1);
    g_esrc[pos] = g_src[e];
}

// ---------------- layer1 aggregation: warp per dst node ----------------
__global__ void kagg1(){
    int w    = (blockIdx.x * blockDim.x + threadIdx.x) >> 5;
    int lane = threadIdx.x & 31;
    if (w >= NN) return;
    int d   = w;
    int beg = g_off[d], end = g_off[d + 1];
    float ald0 = g_al1d[d * 2], ald1 = g_al1d[d * 2 + 1];

    // pass 1: per-head max
    float m0 = -CUDART_INF_F, m1 = -CUDART_INF_F;
    for (int j = beg + lane; j < end; j += 32){
        int s = g_esrc[j];
        m0 = fmaxf(m0, lrelu(g_al1s[s * 2]     + ald0));
        m1 = fmaxf(m1, lrelu(g_al1s[s * 2 + 1] + ald1));
    }
    #pragma unroll
    for (int off = 16; off; off >>= 1){
        m0 = fmaxf(m0, __shfl_xor_sync(0xffffffffu, m0, off));
        m1 = fmaxf(m1, __shfl_xor_sync(0xffffffffu, m1, off));
    }
    // pass 2: denom
    float den0 = 0.f, den1 = 0.f;
    for (int j = beg + lane; j < end; j += 32){
        int s = g_esrc[j];
        den0 += __expf(lrelu(g_al1s[s * 2]     + ald0) - m0);
        den1 += __expf(lrelu(g_al1s[s * 2 + 1] + ald1) - m1);
    }
    #pragma unroll
    for (int off = 16; off; off >>= 1){
        den0 += __shfl_xor_sync(0xffffffffu, den0, off);
        den1 += __shfl_xor_sync(0xffffffffu, den1, off);
    }
    // pass 3: channel-parallel weighted gather (lane owns 4 of 128 channels)
    int   h    = lane >> 4;                    // 0 for ch 0-63, 1 for ch 64-127
    float ald  = h ? ald1 : ald0;
    float mh   = h ? m1 : m0;
    float rden = 1.f / (h ? den1 : den0);
    float a0 = 0.f, a1 = 0.f, a2 = 0.f, a3 = 0.f;
    for (int j = beg; j < end; j++){
        int   s     = g_esrc[j];
        float alpha = __expf(lrelu(g_al1s[s * 2 + h] + ald) - mh) * rden;
        float4 v = *reinterpret_cast<const float4*>(g_xw1 + s * F1 + lane * 4);
        a0 = fmaf(v.x, alpha, a0); a1 = fmaf(v.y, alpha, a1);
        a2 = fmaf(v.z, alpha, a2); a3 = fmaf(v.w, alpha, a3);
    }
    *reinterpret_cast<float4*>(g_hacc + d * F1 + lane * 4) = make_float4(a0, a1, a2, a3);
}

// ---------------- fused layer1 epilogue + layer2 projection ----------------
__global__ void k5(const float* __restrict__ b1, const float* __restrict__ W2,
                   const float* __restrict__ as2, const float* __restrict__ ad2){
    __shared__ float sh[F1];
    __shared__ float rs[2], rd[2];
    int n = blockIdx.x, t = threadIdx.x;           // 64 threads
    sh[t]      = fmaxf(g_hacc[n * F1 + t]      + b1[t],      0.f);
    sh[t + 64] = fmaxf(g_hacc[n * F1 + 64 + t] + b1[64 + t], 0.f);
    __syncthreads();
    float acc = 0.f;
    #pragma unroll 8
    for (int k = 0; k < F1; k++) acc = fmaf(sh[k], W2[k * F2 + t], acc);
    g_xw2[n * F2 + t] = acc;
    float ps = acc * as2[t], pd = acc * ad2[t];
    #pragma unroll
    for (int off = 16; off; off >>= 1){
        ps += __shfl_down_sync(0xffffffffu, ps, off);
        pd += __shfl_down_sync(0xffffffffu, pd, off);
    }
    if ((t & 31) == 0){ rs[t >> 5] = ps; rd[t >> 5] = pd; }
    __syncthreads();
    if (t == 0){ g_al2s[n] = rs[0] + rs[1]; g_al2d[n] = rd[0] + rd[1]; }
}

// ---------------- layer2 aggregation: warp per dst node ----------------
__global__ void kagg2(float* __restrict__ out, const float* __restrict__ b2){
    int w    = (blockIdx.x * blockDim.x + threadIdx.x) >> 5;
    int lane = threadIdx.x & 31;
    if (w >= NN) return;
    int d   = w;
    int beg = g_off[d], end = g_off[d + 1];
    float ald = g_al2d[d];

    float m = -CUDART_INF_F;
    for (int j = beg + lane; j < end; j += 32)
        m = fmaxf(m, lrelu(g_al2s[g_esrc[j]] + ald));
    #pragma unroll
    for (int off = 16; off; off >>= 1)
        m = fmaxf(m, __shfl_xor_sync(0xffffffffu, m, off));

    float den = 0.f;
    for (int j = beg + lane; j < end; j += 32)
        den += __expf(lrelu(g_al2s[g_esrc[j]] + ald) - m);
    #pragma unroll
    for (int off = 16; off; off >>= 1)
        den += __shfl_xor_sync(0xffffffffu, den, off);
    float rden = 1.f / den;

    float a0 = 0.f, a1 = 0.f;                      // lane owns 2 of 64 channels
    for (int j = beg; j < end; j++){
        int   s     = g_esrc[j];
        float alpha = __expf(lrelu(g_al2s[s] + ald) - m) * rden;
        float2 v = *reinterpret_cast<const float2*>(g_xw2 + s * F2 + lane * 2);
        a0 = fmaf(v.x, alpha, a0);
        a1 = fmaf(v.y, alpha, a1);
    }
    float2 r = make_float2(a0 + b2[lane * 2], a1 + b2[lane * 2 + 1]);
    *reinterpret_cast<float2*>(out + d * F2 + lane * 2) = r;
}

extern "C" void kernel_launch(void* const* d_in, const int* in_sizes, int n_in,
                              void* d_out, int out_size){
    const float* x   = (const float*)d_in[0];
    const void*  ei  = d_in[1];
    const float* W1  = (const float*)d_in[2];
    const float* as1 = (const float*)d_in[3];
    const float* ad1 = (const float*)d_in[4];
    const float* b1  = (const float*)d_in[5];
    const float* W2  = (const float*)d_in[6];
    const float* as2 = (const float*)d_in[7];
    const float* ad2 = (const float*)d_in[8];
    const float* b2  = (const float*)d_in[9];
    float* out = (float*)d_out;

    int eb = (ETOT + 255) / 256;
    int wb = (NN * 32 + 255) / 256;                // warp-per-node grids

    kdetect<<<1, 1>>>(ei);
    kinit<<<(NN + 255) / 256, 256>>>();
    kconv<<<eb, 256>>>(ei);
    k1<<<NN, 128>>>(x, W1, as1, ad1);
    kscan<<<1, 1024>>>();
    kscatter<<<eb, 256>>>();
    kagg1<<<wb, 256>>>();
    k5<<<NN, 64>>>(b1, W2, as2, ad2);
    kagg2<<<wb, 256>>>(out, b2);
}